// round 14
// baseline (speedup 1.0000x reference)
#include <cuda_runtime.h>

#define WS    11
#define TILE  32
#define IN    42
#define SAPAD 46
#define HPAD  33
#define NC    48

#define SA_BYTES (IN * SAPAD * 8)      // 15456
#define HC_BYTES (IN * HPAD * 16)      // 22176

typedef unsigned long long u64;

// ---------------- packed f32x2 helpers --------------------------------------
__device__ __forceinline__ u64 pack2(float lo, float hi) {
    u64 r; asm("mov.b64 %0, {%1, %2};" : "=l"(r) : "f"(lo), "f"(hi)); return r;
}
__device__ __forceinline__ float2 unpack2(u64 v) {
    float2 f; asm("mov.b64 {%0, %1}, %2;" : "=f"(f.x), "=f"(f.y) : "l"(v)); return f;
}
__device__ __forceinline__ u64 fma2(u64 a, u64 b, u64 c) {
    u64 d; asm("fma.rn.f32x2 %0, %1, %2, %3;" : "=l"(d) : "l"(a), "l"(b), "l"(c)); return d;
}
__device__ __forceinline__ u64 add2(u64 a, u64 b) {
    u64 d; asm("add.rn.f32x2 %0, %1, %2;" : "=l"(d) : "l"(a), "l"(b)); return d;
}
__device__ __forceinline__ u64 mul2(u64 a, u64 b) {
    u64 d; asm("mul.rn.f32x2 %0, %1, %2;" : "=l"(d) : "l"(a), "l"(b)); return d;
}

// ---------------- scratch ----------------------------------------------------
// All data (inputs staged, pooled pyramids) lives in the rotated basis
// (u, v) = (x+y, x-y). Pooling is linear so the pyramid stays in (u,v).
// Zero-initialized at module load; final_kernel re-zeroes after consuming.
__device__ float g_cs_sum[5][NC];
__device__ float g_ssim_sum[5][NC];
__device__ u64 g_s1[NC * 256 * 256];
__device__ u64 g_s2[NC * 128 * 128];
__device__ u64 g_s3[NC * 64 * 64];
__device__ u64 g_s4[NC * 32 * 32];

// ======== ssim core pieces ===================================================
#define SSIM_SHARED \
    __shared__ __align__(16) char smem_raw[SA_BYTES + HC_BYTES]; \
    u64 (*sA)[SAPAD] = reinterpret_cast<u64(*)[SAPAD]>(smem_raw); \
    ulonglong2 (*hC)[HPAD] = reinterpret_cast<ulonglong2(*)[HPAD]>(smem_raw + SA_BYTES); \
    __shared__ float tg_s[WS]; \
    __shared__ float red[16];

#define SSIM_TAPS \
    if (tid < WS) tg_s[tid] = win[tid * WS + 5] * rsqrtf(win[5 * WS + 5]);

#define SSIM_WP \
    u64 wp[6]; \
    _Pragma("unroll") \
    for (int k = 0; k < 6; k++) { float w = tg_s[k]; wp[k] = pack2(w, w); }

#define WSYM(k) wp[(k) < 6 ? (k) : 10 - (k)]

// horizontal conv over sA row R, cols C0..C0+13 -> hC[R][C0..C0+3]
// plane 1: (u, v); plane 2: (u^2, v^2) = mul2(a, a) -- single packed op.
#define SSIM_HORIZ_RC(R, C0) { \
    int hr = (R); int hc0 = (C0); \
    u64 a1v[4] = {0,0,0,0}, a2v[4] = {0,0,0,0}; \
    const ulonglong2* hp = (const ulonglong2*)&sA[hr][0] + (hc0 >> 1); \
    ulonglong2 pr = hp[0]; \
    _Pragma("unroll") \
    for (int jp = 0; jp < 7; jp++) { \
        ulonglong2 nxt; \
        if (jp < 6) nxt = hp[jp + 1]; \
        _Pragma("unroll") \
        for (int e = 0; e < 2; e++) { \
            int j = 2 * jp + e; \
            u64 a = e ? pr.y : pr.x; \
            u64 q = mul2(a, a); \
            _Pragma("unroll") \
            for (int o = 0; o < 4; o++) { \
                int k = j - o; \
                if (k >= 0 && k < WS) { \
                    a1v[o] = fma2(WSYM(k), a, a1v[o]); \
                    a2v[o] = fma2(WSYM(k), q, a2v[o]); \
                } \
            } \
        } \
        pr = nxt; \
    } \
    _Pragma("unroll") \
    for (int o = 0; o < 4; o++) hC[hr][hc0 + o] = make_ulonglong2(a1v[o], a2v[o]); \
}

// main batch: warp = col-group, lane = row (shift/mask only, conflict-free)
#define SSIM_HORIZ_MAIN SSIM_HORIZ_RC((tid & 31), (tid >> 5) * 4)
// tail: 80 tasks, rows 32..41 x 8 groups
#define SSIM_HORIZ_TAIL { int tg_ = tid / 10; SSIM_HORIZ_RC(32 + tid - tg_ * 10, tg_ * 4) }

// epilogue identities (u,v basis):
//   A = E[u^2]-mu^2 = sig_u^2, B = sig_v^2
//   cs = (A-B+2C2)/(A+B+2C2); ss = (mu^2-mv^2+2C1)/(mu^2+mv^2+2C1)*cs
#define SSIM_VERT_AND_REDUCE(OVAL, SCALE) \
    float ssim_acc = 0.f, cs_acc = 0.f; \
    { \
        int c = threadIdx.x; \
        int rbase = threadIdx.y * 4; \
        u64 a1v[4] = {0,0,0,0}, a2v[4] = {0,0,0,0}; \
        const ulonglong2* vp = &hC[rbase][c]; \
        ulonglong2 hv = vp[0]; \
        _Pragma("unroll") \
        for (int j = 0; j < 14; j++) { \
            ulonglong2 nxt; \
            if (j < 13) nxt = vp[(j + 1) * HPAD]; \
            _Pragma("unroll") \
            for (int o = 0; o < 4; o++) { \
                int k = j - o; \
                if (k >= 0 && k < WS) { \
                    a1v[o] = fma2(WSYM(k), hv.x, a1v[o]); \
                    a2v[o] = fma2(WSYM(k), hv.y, a2v[o]); \
                } \
            } \
            hv = nxt; \
        } \
        bool colv = (ox0 + c) < (OVAL); \
        _Pragma("unroll") \
        for (int o = 0; o < 4; o++) { \
            if (colv && (oy0 + rbase + o) < (OVAL)) { \
                float2 m = unpack2(a1v[o]); \
                float2 e = unpack2(a2v[o]); \
                float mu2 = m.x * m.x, mv2 = m.y * m.y; \
                float A = e.x - mu2, B = e.y - mv2; \
                const float C1x2 = 2e-4f, C2x2 = 1.8e-3f; \
                float cs = __fdividef(A - B + C2x2, A + B + C2x2); \
                float ss = __fdividef(mu2 - mv2 + C1x2, mu2 + mv2 + C1x2) * cs; \
                cs_acc += cs; ssim_acc += ss; \
            } \
        } \
    } \
    _Pragma("unroll") \
    for (int o = 16; o > 0; o >>= 1) { \
        ssim_acc += __shfl_down_sync(0xffffffffu, ssim_acc, o); \
        cs_acc   += __shfl_down_sync(0xffffffffu, cs_acc, o); \
    } \
    if (threadIdx.x == 0) { red[threadIdx.y] = ssim_acc; red[8 + threadIdx.y] = cs_acc; } \
    __syncthreads(); \
    if (tid == 0) { \
        float s = 0.f, cc = 0.f; \
        _Pragma("unroll") \
        for (int i = 0; i < 8; i++) { s += red[i]; cc += red[8 + i]; } \
        atomicAdd(&g_ssim_sum[SCALE][nc], s); \
        atomicAdd(&g_cs_sum[SCALE][nc], cc); \
    }

// ======== scale 0: ssim + full pool chain in the tail ========================
__global__ __launch_bounds__(256, 6) void ssim_scale0(
    const float* __restrict__ x0, const float* __restrict__ y0,
    const float* __restrict__ win) {
    SSIM_SHARED
    int b = blockIdx.x;
    int nc = b >> 8;
    int r0 = b & 255;
    int by = r0 >> 4, bx = r0 & 15;
    const float* xb = x0 + (size_t)nc * 262144;
    const float* yb = y0 + (size_t)nc * 262144;
    int ox0 = bx * 32, oy0 = by * 32;
    int tid = threadIdx.y * 32 + threadIdx.x;

    SSIM_TAPS

    // staging: rotate to (u,v) = (x+y, x-y) at load
#pragma unroll
    for (int it = 0; it < 2; it++) {
        int t = tid + it * 256;
        if (t < 462) {
            int r = t / 11;
            int g = t - r * 11;
            int gy = oy0 + r;
            int gxq = ox0 + g * 4;
            float4 xq = make_float4(0.f, 0.f, 0.f, 0.f), yq = xq;
            if (gy < 512 && gxq < 512) {
                xq = *(const float4*)(xb + (size_t)gy * 512 + gxq);
                yq = *(const float4*)(yb + (size_t)gy * 512 + gxq);
            }
            ulonglong2* dst = (ulonglong2*)&sA[r][g * 4];
            dst[0] = make_ulonglong2(pack2(xq.x + yq.x, xq.x - yq.x),
                                     pack2(xq.y + yq.y, xq.y - yq.y));
            dst[1] = make_ulonglong2(pack2(xq.z + yq.z, xq.z - yq.z),
                                     pack2(xq.w + yq.w, xq.w - yq.w));
        }
    }
    __syncthreads();

    SSIM_WP
    SSIM_HORIZ_MAIN
    if (tid < 80) SSIM_HORIZ_TAIL
    __syncthreads();

    SSIM_VERT_AND_REDUCE(502, 0)

    // ---- pool chain tail: sA intact (holds u,v); hC dead -> scratch ----
    u64* scr1 = (u64*)(smem_raw + SA_BYTES);
    u64* scr2 = scr1 + 256;
    u64* scr3 = scr2 + 64;
    u64 quarter = pack2(0.25f, 0.25f);
    {
        int i = tid >> 4, j = tid & 15;
        u64 s = mul2(add2(add2(sA[2*i][2*j], sA[2*i][2*j+1]),
                          add2(sA[2*i+1][2*j], sA[2*i+1][2*j+1])), quarter);
        scr1[tid] = s;
        g_s1[(size_t)nc * 65536 + (size_t)(by * 16 + i) * 256 + (bx * 16 + j)] = s;
    }
    __syncthreads();
    if (tid < 64) {
        int i = tid >> 3, j = tid & 7;
        u64 s = mul2(add2(add2(scr1[(2*i)*16 + 2*j], scr1[(2*i)*16 + 2*j + 1]),
                          add2(scr1[(2*i+1)*16 + 2*j], scr1[(2*i+1)*16 + 2*j + 1])), quarter);
        scr2[tid] = s;
        g_s2[(size_t)nc * 16384 + (size_t)(by * 8 + i) * 128 + (bx * 8 + j)] = s;
    }
    __syncthreads();
    if (tid < 16) {
        int i = tid >> 2, j = tid & 3;
        u64 s = mul2(add2(add2(scr2[(2*i)*8 + 2*j], scr2[(2*i)*8 + 2*j + 1]),
                          add2(scr2[(2*i+1)*8 + 2*j], scr2[(2*i+1)*8 + 2*j + 1])), quarter);
        scr3[tid] = s;
        g_s3[(size_t)nc * 4096 + (size_t)(by * 4 + i) * 64 + (bx * 4 + j)] = s;
    }
    __syncthreads();
    if (tid < 4) {
        int i = tid >> 1, j = tid & 1;
        u64 s = mul2(add2(add2(scr3[(2*i)*4 + 2*j], scr3[(2*i)*4 + 2*j + 1]),
                          add2(scr3[(2*i+1)*4 + 2*j], scr3[(2*i+1)*4 + 2*j + 1])), quarter);
        g_s4[(size_t)nc * 1024 + (size_t)(by * 2 + i) * 32 + (bx * 2 + j)] = s;
    }
}

// ======== scales 1-4 (pyramid already in (u,v)) ==============================
__global__ __launch_bounds__(256, 6) void ssim_rest(const float* __restrict__ win) {
    SSIM_SHARED
    int b = blockIdx.x;
    int D, O, nc, bx, by, scale;
    const u64* src;
    if (b < 3072)      { scale = 1; D = 256; O = 246; int l = b;        nc = l >> 6; int r = l & 63; by = r >> 3; bx = r & 7; src = g_s1; }
    else if (b < 3840) { scale = 2; D = 128; O = 118; int l = b - 3072; nc = l >> 4; int r = l & 15; by = r >> 2; bx = r & 3; src = g_s2; }
    else if (b < 4032) { scale = 3; D = 64;  O = 54;  int l = b - 3840; nc = l >> 2; int r = l & 3;  by = r >> 1; bx = r & 1; src = g_s3; }
    else               { scale = 4; D = 32;  O = 22;  int l = b - 4032; nc = l;      by = 0;         bx = 0;      src = g_s4; }
    src += (size_t)nc * D * D;
    int ox0 = bx * 32, oy0 = by * 32;
    int tid = threadIdx.y * 32 + threadIdx.x;

    SSIM_TAPS

#pragma unroll
    for (int it = 0; it < 2; it++) {
        int t = tid + it * 256;
        if (t < 462) {
            int r = t / 11;
            int g = t - r * 11;
            int gy = oy0 + r;
            int gxq = ox0 + g * 4;
            ulonglong2 p0 = make_ulonglong2(0ull, 0ull), p1 = p0;
            if (gy < D && gxq < D) {
                const ulonglong2* rp = (const ulonglong2*)(src + (size_t)gy * D + gxq);
                p0 = rp[0]; p1 = rp[1];
            }
            ulonglong2* dst = (ulonglong2*)&sA[r][g * 4];
            dst[0] = p0; dst[1] = p1;
        }
    }
    __syncthreads();

    SSIM_WP
    SSIM_HORIZ_MAIN
    if (tid < 80) SSIM_HORIZ_TAIL
    __syncthreads();

    SSIM_VERT_AND_REDUCE(O, scale)
}

// ---------------- final: parallel pow, product, mean; then re-zero ----------
__global__ void final_kernel(const float* __restrict__ weights, float* __restrict__ out) {
    __shared__ float pw[5][NC];
    __shared__ float vals[NC];
    int t = threadIdx.x;
    const float invA[5] = {1.f/(502.f*502.f), 1.f/(246.f*246.f), 1.f/(118.f*118.f),
                           1.f/(54.f*54.f),   1.f/(22.f*22.f)};
    if (t < 5 * NC) {
        int s = t / NC, i = t - s * NC;
        float m = (s < 4) ? g_cs_sum[s][i] : g_ssim_sum[s][i];
        m *= invA[s];
        if (s < 4) m = fmaxf(m, 0.f);
        pw[s][i] = __powf(m, weights[s]);
    }
    __syncthreads();
    if (t < 5 * NC) { (&g_cs_sum[0][0])[t] = 0.f; (&g_ssim_sum[0][0])[t] = 0.f; }
    if (t < NC) vals[t] = pw[0][t] * pw[1][t] * pw[2][t] * pw[3][t] * pw[4][t];
    __syncthreads();
    if (t < 32) {
        float s = vals[t] + ((t < 16) ? vals[t + 32] : 0.f);
#pragma unroll
        for (int o = 16; o > 0; o >>= 1) s += __shfl_down_sync(0xffffffffu, s, o);
        if (t == 0) out[0] = s / (float)NC;
    }
}

// ---------------- launch -----------------------------------------------------
extern "C" void kernel_launch(void* const* d_in, const int* in_sizes, int n_in,
                              void* d_out, int out_size) {
    const float* x   = (const float*)d_in[0];
    const float* y   = (const float*)d_in[1];
    const float* win = (const float*)d_in[2];
    const float* wts = (const float*)d_in[3];
    float* out = (float*)d_out;

    ssim_scale0<<<12288, dim3(32, 8)>>>(x, y, win);
    ssim_rest<<<4080, dim3(32, 8)>>>(win);
    final_kernel<<<1, 256>>>(wts, out);
}

// round 15
// speedup vs baseline: 1.5509x; 1.5509x over previous
#include <cuda_runtime.h>

#define WS    11
#define TILE  32
#define IN    42
#define SAPAD 46
#define HPAD  33
#define NC    48

#define SA_BYTES (IN * SAPAD * 8)      // 15456
#define HC_BYTES (IN * HPAD * 16)      // 22176

typedef unsigned long long u64;

// ---------------- packed f32x2 helpers --------------------------------------
__device__ __forceinline__ u64 pack2(float lo, float hi) {
    u64 r; asm("mov.b64 %0, {%1, %2};" : "=l"(r) : "f"(lo), "f"(hi)); return r;
}
__device__ __forceinline__ float2 unpack2(u64 v) {
    float2 f; asm("mov.b64 {%0, %1}, %2;" : "=f"(f.x), "=f"(f.y) : "l"(v)); return f;
}
__device__ __forceinline__ u64 fma2(u64 a, u64 b, u64 c) {
    u64 d; asm("fma.rn.f32x2 %0, %1, %2, %3;" : "=l"(d) : "l"(a), "l"(b), "l"(c)); return d;
}
__device__ __forceinline__ u64 add2(u64 a, u64 b) {
    u64 d; asm("add.rn.f32x2 %0, %1, %2;" : "=l"(d) : "l"(a), "l"(b)); return d;
}
__device__ __forceinline__ u64 mul2(u64 a, u64 b) {
    u64 d; asm("mul.rn.f32x2 %0, %1, %2;" : "=l"(d) : "l"(a), "l"(b)); return d;
}

// ---------------- scratch ----------------------------------------------------
// Zero-initialized at module load; final_kernel re-zeroes after consuming.
__device__ float g_cs_sum[5][NC];
__device__ float g_ssim_sum[5][NC];
__device__ u64 g_s1[NC * 256 * 256];
__device__ u64 g_s2[NC * 128 * 128];
__device__ u64 g_s3[NC * 64 * 64];
__device__ u64 g_s4[NC * 32 * 32];

// ======== ssim core pieces ===================================================
#define SSIM_SHARED \
    __shared__ __align__(16) char smem_raw[SA_BYTES + HC_BYTES]; \
    u64 (*sA)[SAPAD] = reinterpret_cast<u64(*)[SAPAD]>(smem_raw); \
    ulonglong2 (*hC)[HPAD] = reinterpret_cast<ulonglong2(*)[HPAD]>(smem_raw + SA_BYTES); \
    __shared__ float tg_s[WS]; \
    __shared__ float red[16];

#define SSIM_TAPS \
    if (tid < WS) tg_s[tid] = win[tid * WS + 5] * rsqrtf(win[5 * WS + 5]);

#define SSIM_WP \
    u64 wp[6]; \
    _Pragma("unroll") \
    for (int k = 0; k < 6; k++) { float w = tg_s[k]; wp[k] = pack2(w, w); }

#define WSYM(k) wp[(k) < 6 ? (k) : 10 - (k)]

// horizontal conv over sA row R, cols C0..C0+13 -> hC[R][C0..C0+3]
#define SSIM_HORIZ_RC(R, C0) { \
    int hr = (R); int hc0 = (C0); \
    u64 a1v[4] = {0,0,0,0}, a2v[4] = {0,0,0,0}; \
    const ulonglong2* hp = (const ulonglong2*)&sA[hr][0] + (hc0 >> 1); \
    ulonglong2 pr = hp[0]; \
    _Pragma("unroll") \
    for (int jp = 0; jp < 7; jp++) { \
        ulonglong2 nxt; \
        if (jp < 6) nxt = hp[jp + 1]; \
        _Pragma("unroll") \
        for (int e = 0; e < 2; e++) { \
            int j = 2 * jp + e; \
            u64 a = e ? pr.y : pr.x; \
            float2 v = unpack2(a); \
            u64 q = pack2(fmaf(v.x, v.x, v.y * v.y), v.x * v.y); \
            _Pragma("unroll") \
            for (int o = 0; o < 4; o++) { \
                int k = j - o; \
                if (k >= 0 && k < WS) { \
                    a1v[o] = fma2(WSYM(k), a, a1v[o]); \
                    a2v[o] = fma2(WSYM(k), q, a2v[o]); \
                } \
            } \
        } \
        pr = nxt; \
    } \
    _Pragma("unroll") \
    for (int o = 0; o < 4; o++) hC[hr][hc0 + o] = make_ulonglong2(a1v[o], a2v[o]); \
}

// main batch: warp = col-group, lane = row (shift/mask only, conflict-free)
#define SSIM_HORIZ_MAIN SSIM_HORIZ_RC((tid & 31), (tid >> 5) * 4)
// tail: 80 tasks, rows 32..41 x 8 groups
#define SSIM_HORIZ_TAIL { int tg_ = tid / 10; SSIM_HORIZ_RC(32 + tid - tg_ * 10, tg_ * 4) }

#define SSIM_VERT_AND_REDUCE(OVAL, SCALE) \
    float ssim_acc = 0.f, cs_acc = 0.f; \
    { \
        int c = threadIdx.x; \
        int rbase = threadIdx.y * 4; \
        u64 a1v[4] = {0,0,0,0}, a2v[4] = {0,0,0,0}; \
        const ulonglong2* vp = &hC[rbase][c]; \
        ulonglong2 hv = vp[0]; \
        _Pragma("unroll") \
        for (int j = 0; j < 14; j++) { \
            ulonglong2 nxt; \
            if (j < 13) nxt = vp[(j + 1) * HPAD]; \
            _Pragma("unroll") \
            for (int o = 0; o < 4; o++) { \
                int k = j - o; \
                if (k >= 0 && k < WS) { \
                    a1v[o] = fma2(WSYM(k), hv.x, a1v[o]); \
                    a2v[o] = fma2(WSYM(k), hv.y, a2v[o]); \
                } \
            } \
            hv = nxt; \
        } \
        bool colv = (ox0 + c) < (OVAL); \
        _Pragma("unroll") \
        for (int o = 0; o < 4; o++) { \
            if (colv && (oy0 + rbase + o) < (OVAL)) { \
                float2 m = unpack2(a1v[o]); \
                float2 e = unpack2(a2v[o]); \
                float mxx = m.x * m.x, myy = m.y * m.y, mxy = m.x * m.y; \
                float svar = e.x - mxx - myy; \
                float sxy_ = e.y - mxy; \
                const float C1 = 1e-4f, C2 = 9e-4f; \
                float cs = __fdividef(2.f * sxy_ + C2, svar + C2); \
                float ss = __fdividef(2.f * mxy + C1, mxx + myy + C1) * cs; \
                cs_acc += cs; ssim_acc += ss; \
            } \
        } \
    } \
    _Pragma("unroll") \
    for (int o = 16; o > 0; o >>= 1) { \
        ssim_acc += __shfl_down_sync(0xffffffffu, ssim_acc, o); \
        cs_acc   += __shfl_down_sync(0xffffffffu, cs_acc, o); \
    } \
    if (threadIdx.x == 0) { red[threadIdx.y] = ssim_acc; red[8 + threadIdx.y] = cs_acc; } \
    __syncthreads(); \
    if (tid == 0) { \
        float s = 0.f, cc = 0.f; \
        _Pragma("unroll") \
        for (int i = 0; i < 8; i++) { s += red[i]; cc += red[8 + i]; } \
        atomicAdd(&g_ssim_sum[SCALE][nc], s); \
        atomicAdd(&g_cs_sum[SCALE][nc], cc); \
    }

// ======== scale 0: ssim + pool chain (level 1 block-wide, 2-4 warp0) =========
__global__ __launch_bounds__(256, 6) void ssim_scale0(
    const float* __restrict__ x0, const float* __restrict__ y0,
    const float* __restrict__ win) {
    SSIM_SHARED
    int b = blockIdx.x;
    int nc = b >> 8;
    int r0 = b & 255;
    int by = r0 >> 4, bx = r0 & 15;
    const float* xb = x0 + (size_t)nc * 262144;
    const float* yb = y0 + (size_t)nc * 262144;
    int ox0 = bx * 32, oy0 = by * 32;
    int tid = threadIdx.y * 32 + threadIdx.x;

    SSIM_TAPS

#pragma unroll
    for (int it = 0; it < 2; it++) {
        int t = tid + it * 256;
        if (t < 462) {
            int r = t / 11;
            int g = t - r * 11;
            int gy = oy0 + r;
            int gxq = ox0 + g * 4;
            float4 xq = make_float4(0.f, 0.f, 0.f, 0.f), yq = xq;
            if (gy < 512 && gxq < 512) {
                xq = *(const float4*)(xb + (size_t)gy * 512 + gxq);
                yq = *(const float4*)(yb + (size_t)gy * 512 + gxq);
            }
            ulonglong2* dst = (ulonglong2*)&sA[r][g * 4];
            dst[0] = make_ulonglong2(pack2(xq.x, yq.x), pack2(xq.y, yq.y));
            dst[1] = make_ulonglong2(pack2(xq.z, yq.z), pack2(xq.w, yq.w));
        }
    }
    __syncthreads();

    SSIM_WP
    SSIM_HORIZ_MAIN
    if (tid < 80) SSIM_HORIZ_TAIL
    __syncthreads();

    SSIM_VERT_AND_REDUCE(502, 0)
    // (reduce macro ended with __syncthreads: all hC reads complete -> scr reuse safe)

    u64* scr1 = (u64*)(smem_raw + SA_BYTES);
    u64* scr2 = scr1 + 256;
    u64* scr3 = scr2 + 64;
    u64 quarter = pack2(0.25f, 0.25f);

    // level 1: all 256 threads
    {
        int i = tid >> 4, j = tid & 15;
        u64 s = mul2(add2(add2(sA[2*i][2*j], sA[2*i][2*j+1]),
                          add2(sA[2*i+1][2*j], sA[2*i+1][2*j+1])), quarter);
        scr1[tid] = s;
        g_s1[(size_t)nc * 65536 + (size_t)(by * 16 + i) * 256 + (bx * 16 + j)] = s;
    }
    __syncthreads();

    // levels 2-4: warp 0 only, syncwarp-ordered (warps 1-7 exit)
    if (tid < 32) {
        int lane = tid;
#pragma unroll
        for (int h = 0; h < 2; h++) {
            int o = lane + h * 32;
            int i = o >> 3, j = o & 7;
            u64 s = mul2(add2(add2(scr1[(2*i)*16 + 2*j], scr1[(2*i)*16 + 2*j + 1]),
                              add2(scr1[(2*i+1)*16 + 2*j], scr1[(2*i+1)*16 + 2*j + 1])), quarter);
            scr2[o] = s;
            g_s2[(size_t)nc * 16384 + (size_t)(by * 8 + i) * 128 + (bx * 8 + j)] = s;
        }
        __syncwarp();
        if (lane < 16) {
            int i = lane >> 2, j = lane & 3;
            u64 s = mul2(add2(add2(scr2[(2*i)*8 + 2*j], scr2[(2*i)*8 + 2*j + 1]),
                              add2(scr2[(2*i+1)*8 + 2*j], scr2[(2*i+1)*8 + 2*j + 1])), quarter);
            scr3[lane] = s;
            g_s3[(size_t)nc * 4096 + (size_t)(by * 4 + i) * 64 + (bx * 4 + j)] = s;
        }
        __syncwarp();
        if (lane < 4) {
            int i = lane >> 1, j = lane & 1;
            u64 s = mul2(add2(add2(scr3[(2*i)*4 + 2*j], scr3[(2*i)*4 + 2*j + 1]),
                              add2(scr3[(2*i+1)*4 + 2*j], scr3[(2*i+1)*4 + 2*j + 1])), quarter);
            g_s4[(size_t)nc * 1024 + (size_t)(by * 2 + i) * 32 + (bx * 2 + j)] = s;
        }
    }
}

// ======== scales 1-4 =========================================================
__global__ __launch_bounds__(256, 6) void ssim_rest(const float* __restrict__ win) {
    SSIM_SHARED
    int b = blockIdx.x;
    int D, O, nc, bx, by, scale;
    const u64* src;
    if (b < 3072)      { scale = 1; D = 256; O = 246; int l = b;        nc = l >> 6; int r = l & 63; by = r >> 3; bx = r & 7; src = g_s1; }
    else if (b < 3840) { scale = 2; D = 128; O = 118; int l = b - 3072; nc = l >> 4; int r = l & 15; by = r >> 2; bx = r & 3; src = g_s2; }
    else if (b < 4032) { scale = 3; D = 64;  O = 54;  int l = b - 3840; nc = l >> 2; int r = l & 3;  by = r >> 1; bx = r & 1; src = g_s3; }
    else               { scale = 4; D = 32;  O = 22;  int l = b - 4032; nc = l;      by = 0;         bx = 0;      src = g_s4; }
    src += (size_t)nc * D * D;
    int ox0 = bx * 32, oy0 = by * 32;
    int tid = threadIdx.y * 32 + threadIdx.x;

    SSIM_TAPS

#pragma unroll
    for (int it = 0; it < 2; it++) {
        int t = tid + it * 256;
        if (t < 462) {
            int r = t / 11;
            int g = t - r * 11;
            int gy = oy0 + r;
            int gxq = ox0 + g * 4;
            ulonglong2 p0 = make_ulonglong2(0ull, 0ull), p1 = p0;
            if (gy < D && gxq < D) {
                const ulonglong2* rp = (const ulonglong2*)(src + (size_t)gy * D + gxq);
                p0 = rp[0]; p1 = rp[1];
            }
            ulonglong2* dst = (ulonglong2*)&sA[r][g * 4];
            dst[0] = p0; dst[1] = p1;
        }
    }
    __syncthreads();

    SSIM_WP
    SSIM_HORIZ_MAIN
    if (tid < 80) SSIM_HORIZ_TAIL
    __syncthreads();

    SSIM_VERT_AND_REDUCE(O, scale)
}

// ---------------- final: parallel pow, product, mean; then re-zero ----------
__global__ void final_kernel(const float* __restrict__ weights, float* __restrict__ out) {
    __shared__ float pw[5][NC];
    __shared__ float vals[NC];
    int t = threadIdx.x;
    const float invA[5] = {1.f/(502.f*502.f), 1.f/(246.f*246.f), 1.f/(118.f*118.f),
                           1.f/(54.f*54.f),   1.f/(22.f*22.f)};
    if (t < 5 * NC) {
        int s = t / NC, i = t - s * NC;
        float m = (s < 4) ? g_cs_sum[s][i] : g_ssim_sum[s][i];
        m *= invA[s];
        if (s < 4) m = fmaxf(m, 0.f);
        pw[s][i] = __powf(m, weights[s]);
    }
    __syncthreads();
    if (t < 5 * NC) { (&g_cs_sum[0][0])[t] = 0.f; (&g_ssim_sum[0][0])[t] = 0.f; }
    if (t < NC) vals[t] = pw[0][t] * pw[1][t] * pw[2][t] * pw[3][t] * pw[4][t];
    __syncthreads();
    if (t < 32) {
        float s = vals[t] + ((t < 16) ? vals[t + 32] : 0.f);
#pragma unroll
        for (int o = 16; o > 0; o >>= 1) s += __shfl_down_sync(0xffffffffu, s, o);
        if (t == 0) out[0] = s / (float)NC;
    }
}

// ---------------- launch -----------------------------------------------------
extern "C" void kernel_launch(void* const* d_in, const int* in_sizes, int n_in,
                              void* d_out, int out_size) {
    const float* x   = (const float*)d_in[0];
    const float* y   = (const float*)d_in[1];
    const float* win = (const float*)d_in[2];
    const float* wts = (const float*)d_in[3];
    float* out = (float*)d_out;

    ssim_scale0<<<12288, dim3(32, 8)>>>(x, y, win);
    ssim_rest<<<4080, dim3(32, 8)>>>(win);
    final_kernel<<<1, 256>>>(wts, out);
}